// round 2
// baseline (speedup 1.0000x reference)
#include <cuda_runtime.h>

#define NMAX 20000
#define EMAX 320000
#define FDIM 128
#define PHI_COLS 384
#define NRBF 20
#define NPB 4   // nodes per block in the gather kernel

// ---------------- scratch (static __device__, no allocations) ----------------
__device__ __align__(16) float g_T[(size_t)NMAX * FDIM];        // silu(h@W1+b1)
__device__ __align__(16) float g_phi[(size_t)NMAX * PHI_COLS];  // phi
__device__ int   g_deg[NMAX];
__device__ int   g_off[NMAX];
__device__ int   g_cur[NMAX];
__device__ int   g_perm[EMAX];
__device__ int   g_is64;   // 1 if nbrs is int64 pairs, 0 if int32 pairs

// ---------------- nbrs dtype detect + load ----------------
// For int64 layout (values < 2^31), every odd int32 word is 0.
// For int32 layout, odd words are src node ids (random in [0, N)).
__global__ void detect_kernel(const int* __restrict__ w, int nwords) {
    if (threadIdx.x == 0 && blockIdx.x == 0) {
        int any = 0;
        int lim = nwords < 32 ? nwords : 32;
        for (int i = 1; i < lim; i += 2) any |= w[i];
        g_is64 = (any == 0) ? 1 : 0;
    }
}

// returns {dst, src} for edge e
__device__ __forceinline__ int2 edge_pair(const void* __restrict__ nbrs, size_t e, int is64) {
    if (is64) {
        const long long* p = (const long long*)nbrs;
        long long a = p[2 * e], b = p[2 * e + 1];
        return make_int2((int)a, (int)b);
    } else {
        return ((const int2*)nbrs)[e];
    }
}

// ---------------- packed f32x2 helpers (sm_103a) ----------------
typedef unsigned long long ull;

__device__ __forceinline__ ull pk2(float x, float y) {
    ull r; asm("mov.b64 %0, {%1, %2};" : "=l"(r) : "f"(x), "f"(y)); return r;
}
__device__ __forceinline__ float2 upk2(ull a) {
    float2 r; asm("mov.b64 {%0, %1}, %2;" : "=f"(r.x), "=f"(r.y) : "l"(a)); return r;
}
__device__ __forceinline__ ull ffma2(ull a, ull b, ull c) {
    ull d; asm("fma.rn.f32x2 %0, %1, %2, %3;" : "=l"(d) : "l"(a), "l"(b), "l"(c)); return d;
}
__device__ __forceinline__ ull fmul2(ull a, ull b) {
    ull d; asm("mul.rn.f32x2 %0, %1, %2;" : "=l"(d) : "l"(a), "l"(b)); return d;
}
__device__ __forceinline__ ull fadd2(ull a, ull b) {
    ull d; asm("add.rn.f32x2 %0, %1, %2;" : "=l"(d) : "l"(a), "l"(b)); return d;
}

// ---------------- CSR build: zero / histogram / scan / scatter ----------------
__global__ void zero_deg_kernel(int Nn) {
    int i = blockIdx.x * 256 + threadIdx.x;
    if (i < Nn) g_deg[i] = 0;
}

__global__ void hist_kernel(const void* __restrict__ nbrs, int E) {
    int is64 = g_is64;
    int e = blockIdx.x * 256 + threadIdx.x;
    if (e < E) {
        int2 p = edge_pair(nbrs, (size_t)e, is64);
        atomicAdd(&g_deg[p.x], 1);
    }
}

__global__ void scan_kernel(int Nn) {  // single block, 1024 threads
    __shared__ int sh[1024];
    int run = 0;
    for (int base = 0; base < Nn; base += 1024) {
        int i = base + (int)threadIdx.x;
        int v = (i < Nn) ? g_deg[i] : 0;
        sh[threadIdx.x] = v;
        __syncthreads();
        for (int off = 1; off < 1024; off <<= 1) {
            int t = (threadIdx.x >= off) ? sh[threadIdx.x - off] : 0;
            __syncthreads();
            sh[threadIdx.x] += t;
            __syncthreads();
        }
        int excl = sh[threadIdx.x] - v;
        if (i < Nn) { g_off[i] = run + excl; g_cur[i] = run + excl; }
        run += sh[1023];
        __syncthreads();
    }
}

__global__ void scatter_kernel(const void* __restrict__ nbrs, int E) {
    int is64 = g_is64;
    int e = blockIdx.x * 256 + threadIdx.x;
    if (e < E) {
        int2 p = edge_pair(nbrs, (size_t)e, is64);
        int pos = atomicAdd(&g_cur[p.x], 1);
        g_perm[pos] = e;
    }
}

// ---------------- tiled fp32 GEMM (BM=64, BN=64, BK=16, 128 thr, 8x4 micro) ----------------
// mode 0: C = silu(Aext @ B + bias) -> g_T     (M x 128 @ 128 x 128)
// mode 1: C = g_T @ B + bias        -> g_phi   (M x 128 @ 128 x 384)
__global__ __launch_bounds__(128) void gemm_kernel(
    const float* __restrict__ Aext, const float* __restrict__ B,
    const float* __restrict__ bias, int M, int Ncols, int K, int mode)
{
    const float* __restrict__ A = (mode == 0) ? Aext : (const float*)g_T;
    float* C = (mode == 0) ? g_T : g_phi;

    __shared__ float As[16][64];
    __shared__ float Bs[16][64];

    int tid = threadIdx.x;
    int m0 = blockIdx.x * 64;
    int n0 = blockIdx.y * 64;
    int tr = tid >> 4;   // 0..7
    int tc = tid & 15;   // 0..15

    float acc[8][4];
#pragma unroll
    for (int i = 0; i < 8; ++i)
#pragma unroll
        for (int j = 0; j < 4; ++j) acc[i][j] = 0.0f;

    for (int kt = 0; kt < K; kt += 16) {
        // load A tile (64x16), store transposed As[k][m]
#pragma unroll
        for (int l = 0; l < 2; ++l) {
            int q = tid + l * 128;
            int row = q >> 2;            // 0..63
            int kc = (q & 3) * 4;        // 0,4,8,12
            float4 av = make_float4(0.f, 0.f, 0.f, 0.f);
            int gm = m0 + row;
            if (gm < M) av = *(const float4*)&A[(size_t)gm * K + kt + kc];
            As[kc + 0][row] = av.x; As[kc + 1][row] = av.y;
            As[kc + 2][row] = av.z; As[kc + 3][row] = av.w;
        }
        // load B tile (16x64)
#pragma unroll
        for (int l = 0; l < 2; ++l) {
            int q = tid + l * 128;
            int row = q >> 4;            // 0..15
            int cc = (q & 15) * 4;       // 0..60
            *(float4*)&Bs[row][cc] = *(const float4*)&B[(size_t)(kt + row) * Ncols + n0 + cc];
        }
        __syncthreads();
#pragma unroll
        for (int k = 0; k < 16; ++k) {
            float a[8], b[4];
            *(float4*)&a[0] = *(const float4*)&As[k][tr * 8];
            *(float4*)&a[4] = *(const float4*)&As[k][tr * 8 + 4];
            *(float4*)&b[0] = *(const float4*)&Bs[k][tc * 4];
#pragma unroll
            for (int i = 0; i < 8; ++i)
#pragma unroll
                for (int j = 0; j < 4; ++j)
                    acc[i][j] = fmaf(a[i], b[j], acc[i][j]);
        }
        __syncthreads();
    }

    float bv[4];
    *(float4*)bv = *(const float4*)&bias[n0 + tc * 4];
#pragma unroll
    for (int i = 0; i < 8; ++i) {
        int gm = m0 + tr * 8 + i;
        if (gm < M) {
            float4 o;
            o.x = acc[i][0] + bv[0];
            o.y = acc[i][1] + bv[1];
            o.z = acc[i][2] + bv[2];
            o.w = acc[i][3] + bv[3];
            if (mode == 0) {
                o.x = o.x / (1.0f + __expf(-o.x));
                o.y = o.y / (1.0f + __expf(-o.y));
                o.z = o.z / (1.0f + __expf(-o.z));
                o.w = o.w / (1.0f + __expf(-o.w));
            }
            *(float4*)&C[(size_t)gm * Ncols + n0 + tc * 4] = o;
        }
    }
}

// ---------------- gather node kernel ----------------
// 128 threads = 2 edge-slots x 64 threads; thread t owns features (2t, 2t+1).
// Per-thread register-resident Wr columns (packed f32x2); Chebyshev sin recurrence.
__global__ __launch_bounds__(128) void node_kernel(
    const float* __restrict__ v_i, const float* __restrict__ d_ij,
    const float* __restrict__ ur, const void* __restrict__ nbrs,
    const float* __restrict__ Wr, const float* __restrict__ br,
    float* __restrict__ out, int Nn)
{
    int is64 = g_is64;
    int tid = threadIdx.x;
    int sub = tid >> 6;       // edge-slot 0/1
    int t = tid & 63;
    int f0 = t * 2;           // features f0, f0+1

    // Wr columns for this thread's two features, packed: W[c][r] = {Wr[r][c*128+f0], Wr[r][c*128+f0+1]}
    ull W0[NRBF], W1r[NRBF], W2r[NRBF];
#pragma unroll
    for (int r = 0; r < NRBF; ++r) {
        W0[r]  = *(const ull*)&Wr[(size_t)r * PHI_COLS + 0 * FDIM + f0];
        W1r[r] = *(const ull*)&Wr[(size_t)r * PHI_COLS + 1 * FDIM + f0];
        W2r[r] = *(const ull*)&Wr[(size_t)r * PHI_COLS + 2 * FDIM + f0];
    }
    ull B0 = *(const ull*)&br[0 * FDIM + f0];
    ull B1 = *(const ull*)&br[1 * FDIM + f0];
    ull B2 = *(const ull*)&br[2 * FDIM + f0];

    __shared__ float sh[64 * 8];

    for (int nn = 0; nn < NPB; ++nn) {
        int n = blockIdx.x * NPB + nn;
        if (n >= Nn) break;   // uniform across block

        int beg = g_off[n];
        int deg = g_deg[n];

        ull dh = 0ull, dva = 0ull, dvb = 0ull, dvc = 0ull;  // packed {0,0}

        for (int j = sub; j < deg; j += 2) {
            int e = g_perm[beg + j];
            int src = edge_pair(nbrs, (size_t)e, is64).y;
            float d = d_ij[e];
            float u0 = ur[3 * (size_t)e + 0];
            float u1 = ur[3 * (size_t)e + 1];
            float u2 = ur[3 * (size_t)e + 2];

            float x = d * 0.62831853071795864769f;  // pi/5
            float s, c;
            __sincosf(x, &s, &c);
            float fcs = (d < 5.0f) ? 0.5f * (c + 1.0f) : 0.0f;
            float invd = __frcp_rn(d);
            float twoc = c + c;

            // acc_c = sum_n sin(n x) * Wr[n][c*128+f]   (Chebyshev recurrence)
            ull a0 = 0ull, a1 = 0ull, a2 = 0ull;
            float sp = 0.0f, sn = s;
#pragma unroll
            for (int r = 0; r < NRBF; ++r) {
                ull sv = pk2(sn, sn);
                a0 = ffma2(sv, W0[r], a0);
                a1 = ffma2(sv, W1r[r], a1);
                a2 = ffma2(sv, W2r[r], a2);
                float s2 = __fmaf_rn(twoc, sn, -sp);
                sp = sn; sn = s2;
            }

            ull invdv = pk2(invd, invd);
            ull fcv = pk2(fcs, fcs);
            // emb_c = (acc_c/d + br_c) * fcut
            ull e0 = fmul2(ffma2(a0, invdv, B0), fcv);
            ull e1 = fmul2(ffma2(a1, invdv, B1), fcv);
            ull e2 = fmul2(ffma2(a2, invdv, B2), fcv);

            const float* pb = &g_phi[(size_t)src * PHI_COLS + f0];
            ull p0 = *(const ull*)(pb);
            ull p1 = *(const ull*)(pb + FDIM);
            ull p2 = *(const ull*)(pb + 2 * FDIM);

            ull gm0 = fmul2(p0, e0);  // f1
            ull gm1 = fmul2(p1, e1);  // f2
            ull gm2 = fmul2(p2, e2);  // f3

            dh = fadd2(dh, gm2);

            const float* vb = &v_i[(size_t)src * (FDIM * 3) + (size_t)f0 * 3];
            ull vk0 = pk2(vb[0], vb[3]);
            ull vk1 = pk2(vb[1], vb[4]);
            ull vk2 = pk2(vb[2], vb[5]);

            dva = ffma2(gm0, pk2(u0, u0), ffma2(gm1, vk0, dva));
            dvb = ffma2(gm0, pk2(u1, u1), ffma2(gm1, vk1, dvb));
            dvc = ffma2(gm0, pk2(u2, u2), ffma2(gm1, vk2, dvc));
        }

        // combine the two edge-slot partials, slot 0 writes output
        if (sub == 1) {
            float2 h = upk2(dh), a = upk2(dva), b = upk2(dvb), cc = upk2(dvc);
            float* p = &sh[t * 8];
            p[0] = h.x; p[1] = h.y; p[2] = a.x; p[3] = a.y;
            p[4] = b.x; p[5] = b.y; p[6] = cc.x; p[7] = cc.y;
        }
        __syncthreads();
        if (sub == 0) {
            float2 h = upk2(dh), a = upk2(dva), b = upk2(dvb), cc = upk2(dvc);
            const float* p = &sh[t * 8];
            h.x += p[0]; h.y += p[1]; a.x += p[2]; a.y += p[3];
            b.x += p[4]; b.y += p[5]; cc.x += p[6]; cc.y += p[7];

            // dh_i at out[n*128 + f]
            *(float2*)&out[(size_t)n * FDIM + f0] = make_float2(h.x, h.y);
            // dv_i at out[N*128 + n*384 + f*3 + k]
            float* od = out + (size_t)Nn * FDIM + (size_t)n * (FDIM * 3) + (size_t)f0 * 3;
            *(float2*)&od[0] = make_float2(a.x, b.x);
            *(float2*)&od[2] = make_float2(cc.x, a.y);
            *(float2*)&od[4] = make_float2(b.y, cc.y);
        }
        __syncthreads();
    }
}

// ---------------- launch ----------------
extern "C" void kernel_launch(void* const* d_in, const int* in_sizes, int n_in,
                              void* d_out, int out_size) {
    const float* h_i    = (const float*)d_in[0];
    const float* v_i    = (const float*)d_in[1];
    const float* d_ij   = (const float*)d_in[2];
    const float* unit_r = (const float*)d_in[3];
    const void*  nbrs   = (const void*)d_in[4];
    const float* W1     = (const float*)d_in[5];
    const float* b1     = (const float*)d_in[6];
    const float* W2     = (const float*)d_in[7];
    const float* b2     = (const float*)d_in[8];
    const float* Wr     = (const float*)d_in[9];
    const float* br     = (const float*)d_in[10];
    float* out = (float*)d_out;

    int N = in_sizes[0] / FDIM;
    int E = in_sizes[2];

    // detect nbrs dtype (int32 vs int64 pairs)
    detect_kernel<<<1, 32>>>((const int*)nbrs, in_sizes[4]);

    // CSR build (counting sort of edges by dst)
    zero_deg_kernel<<<(N + 255) / 256, 256>>>(N);
    hist_kernel<<<(E + 255) / 256, 256>>>(nbrs, E);
    scan_kernel<<<1, 1024>>>(N);
    scatter_kernel<<<(E + 255) / 256, 256>>>(nbrs, E);

    // node MLP: T = silu(h@W1+b1); phi = T@W2+b2
    gemm_kernel<<<dim3((N + 63) / 64, 2), 128>>>(h_i, W1, b1, N, FDIM, FDIM, 0);
    gemm_kernel<<<dim3((N + 63) / 64, 6), 128>>>(nullptr, W2, b2, N, PHI_COLS, FDIM, 1);

    // fused edge compute + gather
    node_kernel<<<(N + NPB - 1) / NPB, 128>>>(v_i, d_ij, unit_r, nbrs, Wr, br, out, N);
}

// round 5
// speedup vs baseline: 1.1325x; 1.1325x over previous
#include <cuda_runtime.h>

#define NMAX 20000
#define EMAX 320000
#define FDIM 128
#define PHI_COLS 384
#define NRBF 20
#define NPB 4   // nodes per block in the gather kernel

// ---------------- scratch (static __device__, no allocations) ----------------
__device__ __align__(16) float g_T[(size_t)NMAX * FDIM];        // silu(h@W1+b1)
__device__ __align__(16) float g_phi[(size_t)NMAX * PHI_COLS];  // phi
__device__ int   g_deg[NMAX];
__device__ int   g_off[NMAX];
__device__ int   g_cur[NMAX];
__device__ int   g_srcs[EMAX];              // sorted-by-dst: src node id
__device__ float g_sd[EMAX];                // sorted-by-dst: d_ij
__device__ __align__(16) float g_su[(size_t)3 * EMAX];  // sorted-by-dst: unit_r
__device__ int   g_is64;   // 1 if nbrs is int64 pairs, 0 if int32 pairs

// ---------------- nbrs dtype detect ----------------
__global__ void detect_kernel(const int* __restrict__ w, int nwords) {
    if (threadIdx.x == 0 && blockIdx.x == 0) {
        int any = 0;
        int lim = nwords < 32 ? nwords : 32;
        for (int i = 1; i < lim; i += 2) any |= w[i];
        g_is64 = (any == 0) ? 1 : 0;
    }
}

__device__ __forceinline__ int2 edge_pair(const void* __restrict__ nbrs, size_t e, int is64) {
    if (is64) {
        const long long* p = (const long long*)nbrs;
        return make_int2((int)p[2 * e], (int)p[2 * e + 1]);
    } else {
        return ((const int2*)nbrs)[e];
    }
}

// ---------------- packed f32x2 helpers (sm_103a) ----------------
typedef unsigned long long ull;

__device__ __forceinline__ ull pk2(float x, float y) {
    ull r; asm("mov.b64 %0, {%1, %2};" : "=l"(r) : "f"(x), "f"(y)); return r;
}
__device__ __forceinline__ float2 upk2(ull a) {
    float2 r; asm("mov.b64 {%0, %1}, %2;" : "=f"(r.x), "=f"(r.y) : "l"(a)); return r;
}
__device__ __forceinline__ ull ffma2(ull a, ull b, ull c) {
    ull d; asm("fma.rn.f32x2 %0, %1, %2, %3;" : "=l"(d) : "l"(a), "l"(b), "l"(c)); return d;
}
__device__ __forceinline__ ull fmul2(ull a, ull b) {
    ull d; asm("mul.rn.f32x2 %0, %1, %2;" : "=l"(d) : "l"(a), "l"(b)); return d;
}
__device__ __forceinline__ ull fadd2(ull a, ull b) {
    ull d; asm("add.rn.f32x2 %0, %1, %2;" : "=l"(d) : "l"(a), "l"(b)); return d;
}

// ---------------- CSR build ----------------
__global__ void zero_deg_kernel(int Nn) {
    int i = blockIdx.x * 256 + threadIdx.x;
    if (i < Nn) g_deg[i] = 0;
}

__global__ void hist_kernel(const void* __restrict__ nbrs, int E) {
    int is64 = g_is64;
    int e = blockIdx.x * 256 + threadIdx.x;
    if (e < E) {
        int2 p = edge_pair(nbrs, (size_t)e, is64);
        atomicAdd(&g_deg[p.x], 1);
    }
}

// single block, 1024 threads: thread-sequential chunk scan + shuffle block scan
__global__ void scan_kernel(int Nn) {
    __shared__ int warpsum[32];
    int t = threadIdx.x;
    int C = (Nn + 1023) >> 10;          // elements per thread (20 for N=20000)
    if (C > 32) C = 32;
    int base = t * C;
    int vals[32];
    int s = 0;
    for (int k = 0; k < C; ++k) {
        int i = base + k;
        int v = (i < Nn) ? g_deg[i] : 0;
        vals[k] = s;                    // exclusive within chunk
        s += v;
    }
    int lane = t & 31, w = t >> 5;
    int x = s;
    for (int off = 1; off < 32; off <<= 1) {
        int y = __shfl_up_sync(0xFFFFFFFFu, x, off);
        if (lane >= off) x += y;
    }
    if (lane == 31) warpsum[w] = x;
    __syncthreads();
    if (w == 0) {
        int y = warpsum[lane];
        for (int off = 1; off < 32; off <<= 1) {
            int z = __shfl_up_sync(0xFFFFFFFFu, y, off);
            if (lane >= off) y += z;
        }
        warpsum[lane] = y;
    }
    __syncthreads();
    int excl = x - s + ((w > 0) ? warpsum[w - 1] : 0);
    for (int k = 0; k < C; ++k) {
        int i = base + k;
        if (i < Nn) { g_off[i] = excl + vals[k]; g_cur[i] = excl + vals[k]; }
    }
}

// scatter edges into dst-sorted arrays (src, d, unit_r)
__global__ void scatter_kernel(const void* __restrict__ nbrs,
                               const float* __restrict__ d_ij,
                               const float* __restrict__ ur, int E) {
    int is64 = g_is64;
    int e = blockIdx.x * 256 + threadIdx.x;
    if (e < E) {
        int2 p = edge_pair(nbrs, (size_t)e, is64);
        int pos = atomicAdd(&g_cur[p.x], 1);
        g_srcs[pos] = p.y;
        g_sd[pos] = d_ij[e];
        g_su[3 * (size_t)pos + 0] = ur[3 * (size_t)e + 0];
        g_su[3 * (size_t)pos + 1] = ur[3 * (size_t)e + 1];
        g_su[3 * (size_t)pos + 2] = ur[3 * (size_t)e + 2];
    }
}

// ---------------- tiled fp32 GEMM with packed f32x2 micro-kernel ----------------
// mode 0: C = silu(Aext @ B + bias) -> g_T     (M x 128 @ 128 x 128)
// mode 1: C = g_T @ B + bias        -> g_phi   (M x 128 @ 128 x 384)
__global__ __launch_bounds__(128) void gemm_kernel(
    const float* __restrict__ Aext, const float* __restrict__ B,
    const float* __restrict__ bias, int M, int Ncols, int K, int mode)
{
    const float* __restrict__ A = (mode == 0) ? Aext : (const float*)g_T;
    float* C = (mode == 0) ? g_T : g_phi;

    __shared__ __align__(16) float As[16][64];
    __shared__ __align__(16) float Bs[16][64];

    int tid = threadIdx.x;
    int m0 = blockIdx.x * 64;
    int n0 = blockIdx.y * 64;
    int tr = tid >> 4;   // 0..7  -> rows tr*8 .. tr*8+7
    int tc = tid & 15;   // 0..15 -> cols tc*4 .. tc*4+3

    // acc2[i2][j]: packed pair of rows (2*i2, 2*i2+1), column j
    ull acc2[4][4];
#pragma unroll
    for (int i = 0; i < 4; ++i)
#pragma unroll
        for (int j = 0; j < 4; ++j) acc2[i][j] = 0ull;

    for (int kt = 0; kt < K; kt += 16) {
#pragma unroll
        for (int l = 0; l < 2; ++l) {
            int q = tid + l * 128;
            int row = q >> 2;
            int kc = (q & 3) * 4;
            float4 av = make_float4(0.f, 0.f, 0.f, 0.f);
            int gm = m0 + row;
            if (gm < M) av = *(const float4*)&A[(size_t)gm * K + kt + kc];
            As[kc + 0][row] = av.x; As[kc + 1][row] = av.y;
            As[kc + 2][row] = av.z; As[kc + 3][row] = av.w;
        }
#pragma unroll
        for (int l = 0; l < 2; ++l) {
            int q = tid + l * 128;
            int row = q >> 4;
            int cc = (q & 15) * 4;
            *(float4*)&Bs[row][cc] = *(const float4*)&B[(size_t)(kt + row) * Ncols + n0 + cc];
        }
        __syncthreads();
#pragma unroll
        for (int k = 0; k < 16; ++k) {
            ull aa[4];
#pragma unroll
            for (int i = 0; i < 4; ++i)
                aa[i] = *(const ull*)&As[k][tr * 8 + i * 2];
            float b[4];
            *(float4*)&b[0] = *(const float4*)&Bs[k][tc * 4];
#pragma unroll
            for (int j = 0; j < 4; ++j) {
                ull bv = pk2(b[j], b[j]);
#pragma unroll
                for (int i = 0; i < 4; ++i)
                    acc2[i][j] = ffma2(aa[i], bv, acc2[i][j]);
            }
        }
        __syncthreads();
    }

    float bv[4];
    *(float4*)bv = *(const float4*)&bias[n0 + tc * 4];
#pragma unroll
    for (int i2 = 0; i2 < 4; ++i2) {
        float2 c0 = upk2(acc2[i2][0]), c1 = upk2(acc2[i2][1]);
        float2 c2 = upk2(acc2[i2][2]), c3 = upk2(acc2[i2][3]);
        float4 row0 = make_float4(c0.x + bv[0], c1.x + bv[1], c2.x + bv[2], c3.x + bv[3]);
        float4 row1 = make_float4(c0.y + bv[0], c1.y + bv[1], c2.y + bv[2], c3.y + bv[3]);
        if (mode == 0) {
            row0.x = row0.x / (1.0f + __expf(-row0.x));
            row0.y = row0.y / (1.0f + __expf(-row0.y));
            row0.z = row0.z / (1.0f + __expf(-row0.z));
            row0.w = row0.w / (1.0f + __expf(-row0.w));
            row1.x = row1.x / (1.0f + __expf(-row1.x));
            row1.y = row1.y / (1.0f + __expf(-row1.y));
            row1.z = row1.z / (1.0f + __expf(-row1.z));
            row1.w = row1.w / (1.0f + __expf(-row1.w));
        }
        int gm0 = m0 + tr * 8 + i2 * 2;
        if (gm0 < M)     *(float4*)&C[(size_t)gm0 * Ncols + n0 + tc * 4] = row0;
        if (gm0 + 1 < M) *(float4*)&C[(size_t)(gm0 + 1) * Ncols + n0 + tc * 4] = row1;
    }
}

// ---------------- gather node kernel (2-stage software pipeline) ----------------
__global__ __launch_bounds__(128) void node_kernel(
    const float* __restrict__ v_i,
    const float* __restrict__ Wr, const float* __restrict__ br,
    float* __restrict__ out, int Nn)
{
    int tid = threadIdx.x;
    int sub = tid >> 6;       // edge-slot 0/1
    int t = tid & 63;
    int f0 = t * 2;           // features f0, f0+1

    ull W0[NRBF], W1r[NRBF], W2r[NRBF];
#pragma unroll
    for (int r = 0; r < NRBF; ++r) {
        W0[r]  = *(const ull*)&Wr[(size_t)r * PHI_COLS + 0 * FDIM + f0];
        W1r[r] = *(const ull*)&Wr[(size_t)r * PHI_COLS + 1 * FDIM + f0];
        W2r[r] = *(const ull*)&Wr[(size_t)r * PHI_COLS + 2 * FDIM + f0];
    }
    ull B0 = *(const ull*)&br[0 * FDIM + f0];
    ull B1 = *(const ull*)&br[1 * FDIM + f0];
    ull B2 = *(const ull*)&br[2 * FDIM + f0];

    __shared__ float sh[64 * 8];

    for (int nn = 0; nn < NPB; ++nn) {
        int n = blockIdx.x * NPB + nn;
        if (n >= Nn) break;

        int beg = g_off[n];
        int deg = g_deg[n];

        ull dh = 0ull, dva = 0ull, dvb = 0ull, dvc = 0ull;

        // pipeline stage registers
        ull c_p0 = 0, c_p1 = 0, c_p2 = 0, c_v0 = 0, c_v1 = 0, c_v2 = 0;
        float c_d = 1.0f, c_u0 = 0, c_u1 = 0, c_u2 = 0;

        // prologue: load edge 'sub'
        if (sub < deg) {
            int pos = beg + sub;
            int src = g_srcs[pos];
            c_d = g_sd[pos];
            c_u0 = g_su[3 * (size_t)pos + 0];
            c_u1 = g_su[3 * (size_t)pos + 1];
            c_u2 = g_su[3 * (size_t)pos + 2];
            const float* pb = &g_phi[(size_t)src * PHI_COLS + f0];
            c_p0 = *(const ull*)(pb);
            c_p1 = *(const ull*)(pb + FDIM);
            c_p2 = *(const ull*)(pb + 2 * FDIM);
            const float* vb = &v_i[(size_t)src * (FDIM * 3) + (size_t)f0 * 3];
            c_v0 = pk2(vb[0], vb[3]);
            c_v1 = pk2(vb[1], vb[4]);
            c_v2 = pk2(vb[2], vb[5]);
        }

        for (int j = sub; j < deg; j += 2) {
            // capture current stage
            ull p0 = c_p0, p1 = c_p1, p2 = c_p2;
            ull vk0 = c_v0, vk1 = c_v1, vk2 = c_v2;
            float d = c_d, u0 = c_u0, u1 = c_u1, u2 = c_u2;

            // issue next stage loads (overlap with compute below)
            int jn = j + 2;
            if (jn < deg) {
                int pos = beg + jn;
                int src = g_srcs[pos];
                c_d = g_sd[pos];
                c_u0 = g_su[3 * (size_t)pos + 0];
                c_u1 = g_su[3 * (size_t)pos + 1];
                c_u2 = g_su[3 * (size_t)pos + 2];
                const float* pb = &g_phi[(size_t)src * PHI_COLS + f0];
                c_p0 = *(const ull*)(pb);
                c_p1 = *(const ull*)(pb + FDIM);
                c_p2 = *(const ull*)(pb + 2 * FDIM);
                const float* vb = &v_i[(size_t)src * (FDIM * 3) + (size_t)f0 * 3];
                c_v0 = pk2(vb[0], vb[3]);
                c_v1 = pk2(vb[1], vb[4]);
                c_v2 = pk2(vb[2], vb[5]);
            }

            float x = d * 0.62831853071795864769f;  // pi/5
            float s, c;
            __sincosf(x, &s, &c);
            float fcs = (d < 5.0f) ? 0.5f * (c + 1.0f) : 0.0f;
            float invd = __frcp_rn(d);
            float twoc = c + c;

            ull a0 = 0ull, a1 = 0ull, a2 = 0ull;
            float sp = 0.0f, sn = s;
#pragma unroll
            for (int r = 0; r < NRBF; ++r) {
                ull sv = pk2(sn, sn);
                a0 = ffma2(sv, W0[r], a0);
                a1 = ffma2(sv, W1r[r], a1);
                a2 = ffma2(sv, W2r[r], a2);
                float s2 = __fmaf_rn(twoc, sn, -sp);
                sp = sn; sn = s2;
            }

            ull invdv = pk2(invd, invd);
            ull fcv = pk2(fcs, fcs);
            ull e0 = fmul2(ffma2(a0, invdv, B0), fcv);
            ull e1 = fmul2(ffma2(a1, invdv, B1), fcv);
            ull e2 = fmul2(ffma2(a2, invdv, B2), fcv);

            ull gm0 = fmul2(p0, e0);
            ull gm1 = fmul2(p1, e1);
            ull gm2 = fmul2(p2, e2);

            dh = fadd2(dh, gm2);
            dva = ffma2(gm0, pk2(u0, u0), ffma2(gm1, vk0, dva));
            dvb = ffma2(gm0, pk2(u1, u1), ffma2(gm1, vk1, dvb));
            dvc = ffma2(gm0, pk2(u2, u2), ffma2(gm1, vk2, dvc));
        }

        if (sub == 1) {
            float2 h = upk2(dh), a = upk2(dva), b = upk2(dvb), cc = upk2(dvc);
            float* p = &sh[t * 8];
            p[0] = h.x; p[1] = h.y; p[2] = a.x; p[3] = a.y;
            p[4] = b.x; p[5] = b.y; p[6] = cc.x; p[7] = cc.y;
        }
        __syncthreads();
        if (sub == 0) {
            float2 h = upk2(dh), a = upk2(dva), b = upk2(dvb), cc = upk2(dvc);
            const float* p = &sh[t * 8];
            h.x += p[0]; h.y += p[1]; a.x += p[2]; a.y += p[3];
            b.x += p[4]; b.y += p[5]; cc.x += p[6]; cc.y += p[7];

            *(float2*)&out[(size_t)n * FDIM + f0] = make_float2(h.x, h.y);
            float* od = out + (size_t)Nn * FDIM + (size_t)n * (FDIM * 3) + (size_t)f0 * 3;
            *(float2*)&od[0] = make_float2(a.x, b.x);
            *(float2*)&od[2] = make_float2(cc.x, a.y);
            *(float2*)&od[4] = make_float2(b.y, cc.y);
        }
        __syncthreads();
    }
}

// ---------------- launch ----------------
extern "C" void kernel_launch(void* const* d_in, const int* in_sizes, int n_in,
                              void* d_out, int out_size) {
    const float* h_i    = (const float*)d_in[0];
    const float* v_i    = (const float*)d_in[1];
    const float* d_ij   = (const float*)d_in[2];
    const float* unit_r = (const float*)d_in[3];
    const void*  nbrs   = (const void*)d_in[4];
    const float* W1     = (const float*)d_in[5];
    const float* b1     = (const float*)d_in[6];
    const float* W2     = (const float*)d_in[7];
    const float* b2     = (const float*)d_in[8];
    const float* Wr     = (const float*)d_in[9];
    const float* br     = (const float*)d_in[10];
    float* out = (float*)d_out;

    int N = in_sizes[0] / FDIM;
    int E = in_sizes[2];

    detect_kernel<<<1, 32>>>((const int*)nbrs, in_sizes[4]);

    zero_deg_kernel<<<(N + 255) / 256, 256>>>(N);
    hist_kernel<<<(E + 255) / 256, 256>>>(nbrs, E);
    scan_kernel<<<1, 1024>>>(N);
    scatter_kernel<<<(E + 255) / 256, 256>>>(nbrs, d_ij, unit_r, E);

    gemm_kernel<<<dim3((N + 63) / 64, 2), 128>>>(h_i, W1, b1, N, FDIM, FDIM, 0);
    gemm_kernel<<<dim3((N + 63) / 64, 6), 128>>>(nullptr, W2, b2, N, PHI_COLS, FDIM, 1);

    node_kernel<<<(N + NPB - 1) / NPB, 128>>>(v_i, Wr, br, out, N);
}